// round 3
// baseline (speedup 1.0000x reference)
#include <cuda_runtime.h>
#include <math.h>

#define L    128
#define NB   64
#define DD   768
#define IN   64
#define OUTD 64
#define NO   32
#define EPSV 1e-8f
#define NCH  8          // l-chunks for fused route+EM
#define LCH  (L / NCH)  // 16 l per chunk

// ---------------- scratch (device globals) -----------------------------------
__device__ float g_mu_in[L * NB * IN];            // (l, n, i)
__device__ float g_fa[L * NB];                    // (l, n)
__device__ float g_V[(size_t)L * NO * NB * OUTD]; // (l, o, n, j)  64 MB
__device__ float g_mu[NO * NB * OUTD];            // (o, n, j)
__device__ float g_i2v[NO * NB * OUTD];           // 1/(2 var + eps)
__device__ float g_C[NO * NB];                    // routing constant per (o,n)
// partial EM sums per l-chunk
__device__ float g_p1[NO * NB * NCH * OUTD];
__device__ float g_p2[NO * NB * NCH * OUTD];
__device__ float g_p0[NO * NB * NCH];
__device__ float g_pbu[NO * NB * NCH];
__device__ float g_psfa[NB * NCH];

// ---------------- packed f32x2 helpers ---------------------------------------
__device__ __forceinline__ unsigned long long pk(float x, float y) {
    unsigned long long r; asm("mov.b64 %0, {%1, %2};" : "=l"(r) : "f"(x), "f"(y)); return r;
}
__device__ __forceinline__ void fma2(unsigned long long& d, unsigned long long a, unsigned long long b) {
    asm("fma.rn.f32x2 %0, %1, %2, %0;" : "+l"(d) : "l"(a), "l"(b));
}
__device__ __forceinline__ float2 upk(unsigned long long v) {
    float2 r; asm("mov.b64 {%0, %1}, %2;" : "=f"(r.x), "=f"(r.y) : "l"(v)); return r;
}

// ---------------- kernel 1: a_in + mu_in (packed FMA) -------------------------
// grid = L, block = 256. 64(n) x 64(i) GEMM, K=768, 32-wide k tiles.
__global__ __launch_bounds__(256) void front_kernel(
    const float* __restrict__ x,      // (N, L, D)
    const float* __restrict__ Wsc,    // (L, D)
    const float* __restrict__ Bsc,    // (L)
    const float* __restrict__ Wc,     // (L, D, IN)
    const float* __restrict__ Bc)     // (L, IN)
{
    __shared__ __align__(8) float As[32][66];      // [k][n] transposed, n-pairs packable
    __shared__ __align__(16) float Bs[32][64];     // [k][i]

    const int l   = blockIdx.x;
    const int tid = threadIdx.x;
    const int tn  = tid >> 4;   // 0..15 -> n block of 4
    const int tj  = tid & 15;   // 0..15 -> i block of 4

    unsigned long long acc[2][4];
    #pragma unroll
    for (int p = 0; p < 2; p++)
        #pragma unroll
        for (int c = 0; c < 4; c++) acc[p][c] = 0ULL;

    for (int kk = 0; kk < DD; kk += 32) {
        #pragma unroll
        for (int p = 0; p < 8; p++) {
            int e = tid + p * 256;
            int n = e >> 5, k = e & 31;
            As[k][n] = __ldcs(&x[((size_t)n * L + l) * DD + kk + k]);
        }
        #pragma unroll
        for (int p = 0; p < 8; p++) {
            int e = tid + p * 256;
            int k = e >> 6, i = e & 63;
            Bs[k][i] = __ldcs(&Wc[(size_t)l * DD * IN + (size_t)(kk + k) * IN + i]);
        }
        __syncthreads();
        #pragma unroll
        for (int k = 0; k < 32; k++) {
            const float2* ar = reinterpret_cast<const float2*>(&As[k][0]);
            float2 a0 = ar[tn * 2];       // n pair (tn*4, tn*4+1)
            float2 a1 = ar[tn * 2 + 1];   // n pair (tn*4+2, tn*4+3)
            unsigned long long A0, A1;
            asm("mov.b64 %0, {%1, %2};" : "=l"(A0) : "f"(a0.x), "f"(a0.y));
            asm("mov.b64 %0, {%1, %2};" : "=l"(A1) : "f"(a1.x), "f"(a1.y));
            float4 b = reinterpret_cast<const float4*>(&Bs[k][0])[tj];
            unsigned long long B0 = pk(b.x, b.x), B1 = pk(b.y, b.y),
                               B2 = pk(b.z, b.z), B3 = pk(b.w, b.w);
            fma2(acc[0][0], A0, B0); fma2(acc[0][1], A0, B1);
            fma2(acc[0][2], A0, B2); fma2(acc[0][3], A0, B3);
            fma2(acc[1][0], A1, B0); fma2(acc[1][1], A1, B1);
            fma2(acc[1][2], A1, B2); fma2(acc[1][3], A1, B3);
        }
        __syncthreads();
    }

    #pragma unroll
    for (int p = 0; p < 2; p++) {
        #pragma unroll
        for (int c = 0; c < 4; c++) {
            int i = tj * 4 + c;
            float2 v2 = upk(acc[p][c]);
            float bb = Bc[l * IN + i];
            int n0 = tn * 4 + 2 * p;
            float v0 = v2.x + bb, v1 = v2.y + bb;
            g_mu_in[(size_t)l * NB * IN + (size_t)n0 * IN + i]       = v0 * normcdff(v0);
            g_mu_in[(size_t)l * NB * IN + (size_t)(n0 + 1) * IN + i] = v1 * normcdff(v1);
        }
    }

    const int w = tid >> 5, lane = tid & 31;
    for (int n = w; n < NB; n += 8) {
        float s = 0.f;
        const float* xr = x + ((size_t)n * L + l) * DD;
        const float* wr = Wsc + (size_t)l * DD;
        for (int d = lane; d < DD; d += 32) s += xr[d] * wr[d];
        #pragma unroll
        for (int off = 16; off; off >>= 1) s += __shfl_down_sync(0xffffffffu, s, off);
        if (lane == 0) {
            float a = s + Bsc[l];
            g_fa[l * NB + n] = 1.f / (1.f + expf(-a));
        }
    }
}

// ---------------- kernel 2: votes V (packed FMA) ------------------------------
// grid = L*NO, block = 256.
__global__ __launch_bounds__(256) void vote_kernel(
    const float* __restrict__ Wv,    // (L, NO, IN, OUT)
    const float* __restrict__ Bv)    // (L, NO, OUT)
{
    __shared__ __align__(8) float As[64][66];      // [i][n] transposed
    __shared__ __align__(16) float Bs[64][64];     // [i][j]

    const int lo  = blockIdx.x;   // l*32 + o
    const int l   = lo >> 5;
    const int tid = threadIdx.x;

    const float* A = g_mu_in + (size_t)l * NB * IN;
    const float* B = Wv + (size_t)lo * IN * OUTD;

    #pragma unroll
    for (int p = 0; p < 16; p++) {
        int e = tid + p * 256;
        int n = e >> 6, i = e & 63;
        As[i][n] = A[e];                 // transpose into [i][n]
        Bs[e >> 6][e & 63] = __ldcs(&B[e]);
    }
    __syncthreads();

    const int tn = tid >> 4, tj = tid & 15;
    unsigned long long acc[2][4];
    #pragma unroll
    for (int p = 0; p < 2; p++)
        #pragma unroll
        for (int c = 0; c < 4; c++) acc[p][c] = 0ULL;

    #pragma unroll
    for (int i = 0; i < 64; i++) {
        const float2* ar = reinterpret_cast<const float2*>(&As[i][0]);
        float2 a0 = ar[tn * 2];
        float2 a1 = ar[tn * 2 + 1];
        unsigned long long A0, A1;
        asm("mov.b64 %0, {%1, %2};" : "=l"(A0) : "f"(a0.x), "f"(a0.y));
        asm("mov.b64 %0, {%1, %2};" : "=l"(A1) : "f"(a1.x), "f"(a1.y));
        float4 b = reinterpret_cast<const float4*>(&Bs[i][0])[tj];
        unsigned long long B0 = pk(b.x, b.x), B1 = pk(b.y, b.y),
                           B2 = pk(b.z, b.z), B3 = pk(b.w, b.w);
        fma2(acc[0][0], A0, B0); fma2(acc[0][1], A0, B1);
        fma2(acc[0][2], A0, B2); fma2(acc[0][3], A0, B3);
        fma2(acc[1][0], A1, B0); fma2(acc[1][1], A1, B1);
        fma2(acc[1][2], A1, B2); fma2(acc[1][3], A1, B3);
    }

    float4 bias;
    bias.x = __ldcs(&Bv[(size_t)lo * OUTD + tj * 4 + 0]);
    bias.y = __ldcs(&Bv[(size_t)lo * OUTD + tj * 4 + 1]);
    bias.z = __ldcs(&Bv[(size_t)lo * OUTD + tj * 4 + 2]);
    bias.w = __ldcs(&Bv[(size_t)lo * OUTD + tj * 4 + 3]);
    float* Vout = g_V + (size_t)lo * NB * OUTD;
    #pragma unroll
    for (int p = 0; p < 2; p++) {
        float2 vx = upk(acc[p][0]), vy = upk(acc[p][1]),
               vz = upk(acc[p][2]), vw = upk(acc[p][3]);
        int n0 = tn * 4 + 2 * p;
        float4 o0 = make_float4(vx.x + bias.x, vy.x + bias.y, vz.x + bias.z, vw.x + bias.w);
        float4 o1 = make_float4(vx.y + bias.x, vy.y + bias.y, vz.y + bias.z, vw.y + bias.w);
        reinterpret_cast<float4*>(Vout + (size_t)n0 * OUTD)[tj]       = o0;
        reinterpret_cast<float4*>(Vout + (size_t)(n0 + 1) * OUTD)[tj] = o1;
    }
}

// ---------------- kernel 3: E-step 0 (uniform R) ------------------------------
// grid = NO*NB (bid = o*64 + n), block = 64 = 2 warps over l halves.
__global__ __launch_bounds__(64) void em0_kernel(
    const float* __restrict__ bu, const float* __restrict__ bi)
{
    const int bid = blockIdx.x;
    const int o = bid >> 6, n = bid & 63;
    const int w = threadIdx.x >> 5, lane = threadIdx.x & 31;

    float2 s1 = {0.f, 0.f}, s2 = {0.f, 0.f};
    float s0 = 0.f, sbu = 0.f, sfa = 0.f;
    const float2* V2 = reinterpret_cast<const float2*>(g_V);

    const int l0 = w * 64;
    #pragma unroll 4
    for (int li = 0; li < 64; li++) {
        int l = l0 + li;
        float fa = g_fa[l * NB + n];
        float Dv = fa * (1.f / 32.f);
        float2 v = V2[(((size_t)l * NO + o) * NB + n) * 32 + lane];
        s0 += Dv;
        s1.x += Dv * v.x;       s1.y += Dv * v.y;
        s2.x += Dv * v.x * v.x; s2.y += Dv * v.y * v.y;
        sbu += bu[l] * Dv;
        sfa += fa;
    }

    __shared__ float2 sh1[32], sh2[32];
    __shared__ float sh0, shbu, shfa;
    if (w == 1) {
        sh1[lane] = s1; sh2[lane] = s2;
        if (lane == 0) { sh0 = s0; shbu = sbu; shfa = sfa; }
    }
    __syncthreads();
    if (w == 0) {
        s1.x += sh1[lane].x; s1.y += sh1[lane].y;
        s2.x += sh2[lane].x; s2.y += sh2[lane].y;
        s0 += sh0; sbu += shbu; sfa += shfa;

        float denom = s0 + EPSV;
        float mx = s1.x / denom, my = s1.y / denom;
        float vx = fmaxf((s2.x - 2.f * mx * s1.x + mx * mx * s0) / denom, 0.f);
        float vy = fmaxf((s2.y - 2.f * my * s1.y + my * my * s0) / denom, 0.f);
        float a = sbu - bi[o] * (sfa - s0);

        reinterpret_cast<float2*>(g_mu  + (size_t)bid * OUTD)[lane] = make_float2(mx, my);
        reinterpret_cast<float2*>(g_i2v + (size_t)bid * OUTD)[lane] =
            make_float2(1.f / (2.f * vx + EPSV), 1.f / (2.f * vy + EPSV));

        float lv = logf(vx + EPSV) + logf(vy + EPSV);
        #pragma unroll
        for (int off = 16; off; off >>= 1) lv += __shfl_down_sync(0xffffffffu, lv, off);
        if (lane == 0) {
            float lsig = (a > 0.f) ? -log1pf(expf(-a)) : a - log1pf(expf(a));
            g_C[bid] = lsig - 1.f - 0.5f * 3.14159265358979323846f - 0.5f * lv;
        }
    }
}

// ---------------- kernel 4: fused route + EM partial ---------------------------
// grid = NB * NCH (bid = n*NCH + c). block = 256 (8 warps). Warp w handles
// o = s*8 + w for s=0..3; lane handles j = {2*lane, 2*lane+1}.
__global__ __launch_bounds__(256) void re_kernel(const float* __restrict__ bu)
{
    const int bid = blockIdx.x;
    const int n = bid / NCH, c = bid % NCH;
    const int w = threadIdx.x >> 5, lane = threadIdx.x & 31;

    const float2* V2 = reinterpret_cast<const float2*>(g_V);
    const float2* M2 = reinterpret_cast<const float2*>(g_mu);
    const float2* I2 = reinterpret_cast<const float2*>(g_i2v);

    float2 mu[4], iv[4];
    float  Cc[4];
    #pragma unroll
    for (int s = 0; s < 4; s++) {
        int o = s * 8 + w;
        mu[s] = M2[((size_t)o * NB + n) * 32 + lane];
        iv[s] = I2[((size_t)o * NB + n) * 32 + lane];
        Cc[s] = g_C[o * NB + n];
    }

    float2 a1[4] = {}, a2[4] = {};
    float  s0[4] = {}, sbu[4] = {};
    float  sfa = 0.f;

    __shared__ float sh_logit[NO];

    for (int li = 0; li < LCH; li++) {
        int l = c * LCH + li;
        float fa = g_fa[l * NB + n];
        float bul = bu[l];

        float2 v[4];
        #pragma unroll
        for (int s = 0; s < 4; s++) {
            int o = s * 8 + w;
            v[s] = V2[(((size_t)l * NO + o) * NB + n) * 32 + lane];
        }
        #pragma unroll
        for (int s = 0; s < 4; s++) {
            float dx = v[s].x - mu[s].x, dy = v[s].y - mu[s].y;
            float t = dx * dx * iv[s].x + dy * dy * iv[s].y;
            #pragma unroll
            for (int off = 16; off; off >>= 1) t += __shfl_down_sync(0xffffffffu, t, off);
            if (lane == 0) sh_logit[s * 8 + w] = Cc[s] - t;
        }
        __syncthreads();

        // softmax over 32 o (each warp redundantly)
        float lv = sh_logit[lane];
        float mx = lv;
        #pragma unroll
        for (int off = 16; off; off >>= 1) mx = fmaxf(mx, __shfl_xor_sync(0xffffffffu, mx, off));
        float e = expf(lv - mx);
        float ss = e;
        #pragma unroll
        for (int off = 16; off; off >>= 1) ss += __shfl_xor_sync(0xffffffffu, ss, off);
        float rv = e / ss;   // R for o == lane

        #pragma unroll
        for (int s = 0; s < 4; s++) {
            float R = __shfl_sync(0xffffffffu, rv, s * 8 + w);
            float Dv = fa * R;
            a1[s].x += Dv * v[s].x;        a1[s].y += Dv * v[s].y;
            a2[s].x += Dv * v[s].x * v[s].x; a2[s].y += Dv * v[s].y * v[s].y;
            s0[s]  += Dv;
            sbu[s] += bul * Dv;
        }
        sfa += fa;
        __syncthreads();   // protect sh_logit before next iteration's writes
    }

    #pragma unroll
    for (int s = 0; s < 4; s++) {
        int o = s * 8 + w;
        size_t p = ((size_t)o * NB + n) * NCH + c;
        reinterpret_cast<float2*>(g_p1 + p * OUTD)[lane] = a1[s];
        reinterpret_cast<float2*>(g_p2 + p * OUTD)[lane] = a2[s];
        if (lane == 0) { g_p0[p] = s0[s]; g_pbu[p] = sbu[s]; }
    }
    if (w == 0 && lane == 0) g_psfa[n * NCH + c] = sfa;
}

// ---------------- kernel 5: finalize EM ----------------------------------------
// grid = NO*NB (bid = o*64 + n), block = 64 (thread = j).
__global__ __launch_bounds__(64) void fin_kernel(
    const float* __restrict__ bi, int write_out, float* __restrict__ out)
{
    const int bid = blockIdx.x;
    const int o = bid >> 6, n = bid & 63;
    const int j = threadIdx.x;

    float s1 = 0.f, s2 = 0.f;
    #pragma unroll
    for (int cc = 0; cc < NCH; cc++) {
        s1 += g_p1[((size_t)bid * NCH + cc) * OUTD + j];
        s2 += g_p2[((size_t)bid * NCH + cc) * OUTD + j];
    }

    __shared__ float sh0, shbu, shfa;
    if (j == 0) {
        float t0 = 0.f, tbu = 0.f, tfa = 0.f;
        #pragma unroll
        for (int cc = 0; cc < NCH; cc++) {
            t0  += g_p0[(size_t)bid * NCH + cc];
            tbu += g_pbu[(size_t)bid * NCH + cc];
            tfa += g_psfa[n * NCH + cc];
        }
        sh0 = t0; shbu = tbu; shfa = tfa;
    }
    __syncthreads();
    float s0 = sh0;

    float denom = s0 + EPSV;
    float m   = s1 / denom;
    float var = fmaxf((s2 - 2.f * m * s1 + m * m * s0) / denom, 0.f);
    float a = shbu - bi[o] * (shfa - s0);

    g_mu[(size_t)bid * OUTD + j]  = m;
    g_i2v[(size_t)bid * OUTD + j] = 1.f / (2.f * var + EPSV);

    float lvv = logf(var + EPSV);
    __shared__ float red[2];
    #pragma unroll
    for (int off = 16; off; off >>= 1) lvv += __shfl_down_sync(0xffffffffu, lvv, off);
    if ((j & 31) == 0) red[j >> 5] = lvv;
    __syncthreads();
    if (j == 0) {
        float slv = red[0] + red[1];
        float lsig = (a > 0.f) ? -log1pf(expf(-a)) : a - log1pf(expf(a));
        g_C[bid] = lsig - 1.f - 0.5f * 3.14159265358979323846f - 0.5f * slv;
    }

    if (write_out) {
        if (j == 0) out[n * NO + o] = a;                         // a_out (N, NO)
        out[NB * NO + ((size_t)n * NO + o) * OUTD + j] = m;      // mu_out (N, NO, OUT)
    }
}

// ---------------- launch --------------------------------------------------------
extern "C" void kernel_launch(void* const* d_in, const int* in_sizes, int n_in,
                              void* d_out, int out_size)
{
    const float* x      = (const float*)d_in[0];
    const float* Wscore = (const float*)d_in[1];
    const float* Bscore = (const float*)d_in[2];
    const float* Wcap   = (const float*)d_in[3];
    const float* Bcap   = (const float*)d_in[4];
    const float* Wvote  = (const float*)d_in[5];
    const float* Bvote  = (const float*)d_in[6];
    const float* bu     = (const float*)d_in[7];
    const float* bi     = (const float*)d_in[8];
    float* out = (float*)d_out;

    front_kernel<<<L, 256>>>(x, Wscore, Bscore, Wcap, Bcap);
    vote_kernel<<<L * NO, 256>>>(Wvote, Bvote);

    // iters = 3: E0(uniform), [route+E]1, [route+E]2(write out)
    em0_kernel<<<NO * NB, 64>>>(bu, bi);
    re_kernel<<<NB * NCH, 256>>>(bu);
    fin_kernel<<<NO * NB, 64>>>(bi, 0, out);
    re_kernel<<<NB * NCH, 256>>>(bu);
    fin_kernel<<<NO * NB, 64>>>(bi, 1, out);
}